// round 13
// baseline (speedup 1.0000x reference)
#include <cuda_runtime.h>
#include <cuda_fp16.h>
#include <cstdint>

// BlockLinear: out = block_diag(blocks) @ inp + bias (fp32 in/out)
//   kA: blocks -> g_Ah fp16  (tiny pre-pass)
//   k2: fused GEMM: CTA = 256m x 64n x 256k, 256 threads, 2 CTAs/SM,
//       B loaded f32 from inp -> fp16 smem in-register; 3-stage ring, 1 sync/iter.
// Error: A and B each rounded once to fp16 -> global RMS rel err ~2.9e-4 (<1e-3).

typedef unsigned int u32;

__device__ __half g_Ah[8 * 256 * 256];

__device__ __forceinline__ u32 smem_u32(const void* p) {
    u32 a;
    asm("{ .reg .u64 t; cvta.to.shared.u64 t, %1; cvt.u32.u64 %0, t; }" : "=r"(a) : "l"(p));
    return a;
}

// ---------------- kernel A: blocks -> fp16 ----------------
__global__ __launch_bounds__(256)
void split_A(const float* __restrict__ blocks)
{
    const int base = (blockIdx.x * 256 + threadIdx.x) * 4;
    float4 v = *(const float4*)(blocks + base);
    __half2 h01 = __floats2half2_rn(v.x, v.y);
    __half2 h23 = __floats2half2_rn(v.z, v.w);
    uint2 ph;
    ph.x = *reinterpret_cast<u32*>(&h01);
    ph.y = *reinterpret_cast<u32*>(&h23);
    *(uint2*)(g_Ah + base) = ph;
}

// ---------------- fused GEMM ----------------
#define BK 32
#define OFF_A  0            // A tile: 256 rows x 64B = 16 KB
#define OFF_B  16384        // B tile: 32 rows x 128B = 4 KB
#define STAGE_STRIDE 20480
#define NSTAGE 3
#define SMEM_BYTES (NSTAGE * STAGE_STRIDE)   // 60 KB

// A tile: row-major m x k fp16, 64B rows, 4x16B chunks, XOR swizzle (verified)
__device__ __forceinline__ u32 soff(u32 r, u32 k) {
    return r * 64u + ((((k >> 3) ^ ((r >> 1) & 3u))) << 4) + ((k & 7u) << 1);
}
__device__ __forceinline__ u32 schunk(u32 r, u32 c) {
    return r * 64u + ((c ^ ((r >> 1) & 3u)) << 4);
}
// B tile: 32 k-rows x 64 n fp16, 128B rows, 8x16B chunks, chunk ^= (k&7)
__device__ __forceinline__ u32 bchunk(u32 k, u32 nc) {
    return k * 128u + ((nc ^ (k & 7u)) << 4);
}

__device__ __forceinline__ void ldsm4(u32& r0, u32& r1, u32& r2, u32& r3, u32 addr) {
    asm volatile("ldmatrix.sync.aligned.m8n8.x4.shared.b16 {%0,%1,%2,%3}, [%4];"
                 : "=r"(r0), "=r"(r1), "=r"(r2), "=r"(r3) : "r"(addr));
}
__device__ __forceinline__ void ldsm4t(u32& r0, u32& r1, u32& r2, u32& r3, u32 addr) {
    asm volatile("ldmatrix.sync.aligned.m8n8.x4.trans.shared.b16 {%0,%1,%2,%3}, [%4];"
                 : "=r"(r0), "=r"(r1), "=r"(r2), "=r"(r3) : "r"(addr));
}
__device__ __forceinline__ void mma16816(float* c, const u32* a, u32 b0, u32 b1) {
    asm volatile(
        "mma.sync.aligned.m16n8k16.row.col.f32.f16.f16.f32 "
        "{%0,%1,%2,%3}, {%4,%5,%6,%7}, {%8,%9}, {%0,%1,%2,%3};"
        : "+f"(c[0]), "+f"(c[1]), "+f"(c[2]), "+f"(c[3])
        : "r"(a[0]), "r"(a[1]), "r"(a[2]), "r"(a[3]), "r"(b0), "r"(b1));
}
__device__ __forceinline__ void cp16(u32 dst, const void* src) {
    asm volatile("cp.async.cg.shared.global [%0], [%1], 16;" :: "r"(dst), "l"(src));
}

__global__ __launch_bounds__(256, 2)
void block_linear_fused(const float* __restrict__ inp,
                        const float* __restrict__ bias,
                        float* __restrict__ out)
{
    extern __shared__ char smem[];
    const u32 sb = smem_u32(smem);

    const int tid  = threadIdx.x;
    const int lane = tid & 31;
    const int wid  = tid >> 5;
    const int wm   = wid;            // 8 warp rows x 32 (wn = 0 for all)

    const int nTile = blockIdx.x;
    const int kblk  = blockIdx.y;
    const int n0    = nTile * 64;

    const __half* Ag = g_Ah + (size_t)kblk * 65536;                 // [256][256] fp16
    const float*  Bg = inp + (size_t)(kblk * 256) * 8192 + n0;      // [256][64] f32 strip
    float*        C  = out + (size_t)(kblk * 256) * 8192 + n0;
    const float*  biasp = bias + kblk * 256;

    // A loader: 256 threads, row = tid (0..255), 4 chunks of 16B
    // B loader: row k = tid>>3 (0..31), chunk nc = tid&7, 8 f32 from global
    const int blr = tid >> 3;
    const int bnc = tid & 7;

    float4 bpf0, bpf1;   // B prefetch registers (8 f32)

    float acc[2][8][4];
    #pragma unroll
    for (int i = 0; i < 2; i++)
        #pragma unroll
        for (int j = 0; j < 8; j++)
            #pragma unroll
            for (int q = 0; q < 4; q++) acc[i][j][q] = 0.f;

    auto ldg_B = [&](int c) {
        const float* p = Bg + (size_t)(c * BK + blr) * 8192 + bnc * 8;
        bpf0 = *(const float4*)(p);
        bpf1 = *(const float4*)(p + 4);
    };
    auto sts_B = [&](int c) {
        __half2 h0 = __floats2half2_rn(bpf0.x, bpf0.y);
        __half2 h1 = __floats2half2_rn(bpf0.z, bpf0.w);
        __half2 h2 = __floats2half2_rn(bpf1.x, bpf1.y);
        __half2 h3 = __floats2half2_rn(bpf1.z, bpf1.w);
        uint4 o;
        o.x = *reinterpret_cast<u32*>(&h0);
        o.y = *reinterpret_cast<u32*>(&h1);
        o.z = *reinterpret_cast<u32*>(&h2);
        o.w = *reinterpret_cast<u32*>(&h3);
        *(uint4*)(smem + (c % NSTAGE) * STAGE_STRIDE + OFF_B + bchunk((u32)blr, (u32)bnc)) = o;
    };
    auto cpa_A = [&](int c) {
        const u32 st = sb + (u32)(c % NSTAGE) * STAGE_STRIDE;
        const int k0 = c * BK;
        #pragma unroll
        for (int ch = 0; ch < 4; ++ch) {
            cp16(st + OFF_A + schunk((u32)tid, (u32)ch),
                 Ag + (size_t)tid * 256 + k0 + ch * 8);
        }
    };

    // ---- prologue: B(0) stored, B(1) in regs, A(0),A(1) committed ----
    ldg_B(0);
    cpa_A(0); asm volatile("cp.async.commit_group;" ::: "memory");
    sts_B(0);
    ldg_B(1);
    cpa_A(1); asm volatile("cp.async.commit_group;" ::: "memory");

    const u32 kl  = (u32)(((lane >> 4) << 3) + (lane & 7));
    const u32 ncl = (u32)((lane >> 3) & 1);

    #pragma unroll 1
    for (int c = 0; c < 8; ++c) {
        asm volatile("cp.async.wait_group 1;" ::: "memory");   // A(c) done
        __syncthreads();   // stage c fully written; stage (c+1)%3 free (read at c-2)

        sts_B(c + 1);                    // stage (c+1)%3 from prefetch regs
        if (c + 2 < 8) ldg_B(c + 2);     // regs free; latency covered by compute(c..c+1)
        if (c + 2 < 8) cpa_A(c + 2);
        asm volatile("cp.async.commit_group;" ::: "memory");   // (empty ok near tail)

        // ---- compute(c) on stage c%3 ----
        const u32 buf = sb + (u32)(c % NSTAGE) * STAGE_STRIDE;
        #pragma unroll
        for (int kk = 0; kk < 2; ++kk) {
            const u32 krow = (u32)(kk * 16);
            const u32 am   = (u32)(wm * 32 + (lane & 15));
            const u32 akr  = krow + (u32)((lane >> 4) << 3);

            u32 aH[2][4], bH[4][4];
            #pragma unroll
            for (int i = 0; i < 2; i++)
                ldsm4(aH[i][0], aH[i][1], aH[i][2], aH[i][3],
                      buf + OFF_A + soff(am + i * 16, akr));
            #pragma unroll
            for (int p = 0; p < 4; p++) {
                const u32 ncb = (u32)(p * 2) + ncl;
                ldsm4t(bH[p][0], bH[p][1], bH[p][2], bH[p][3],
                       buf + OFF_B + bchunk(krow + kl, ncb));
            }
            #pragma unroll
            for (int i = 0; i < 2; i++)
                #pragma unroll
                for (int p = 0; p < 4; p++) {
                    mma16816(acc[i][2*p],   aH[i], bH[p][0], bH[p][2]);
                    mma16816(acc[i][2*p+1], aH[i], bH[p][1], bH[p][3]);
                }
        }
    }

    // ---- epilogue: bias + store (verified mapping, wn=0) ----
    #pragma unroll
    for (int i = 0; i < 2; i++) {
        const int r0 = wm * 32 + i * 16 + (lane >> 2);
        const float b0 = biasp[r0];
        const float b1 = biasp[r0 + 8];
        float* p0 = C + (size_t)r0 * 8192;
        float* p1 = C + (size_t)(r0 + 8) * 8192;
        #pragma unroll
        for (int j = 0; j < 8; j++) {
            const int col = j * 8 + (lane & 3) * 2;
            *(float2*)(p0 + col) = make_float2(acc[i][j][0] + b0, acc[i][j][1] + b0);
            *(float2*)(p1 + col) = make_float2(acc[i][j][2] + b1, acc[i][j][3] + b1);
        }
    }
}

extern "C" void kernel_launch(void* const* d_in, const int* in_sizes, int n_in,
                              void* d_out, int out_size)
{
    const float* inp    = (const float*)d_in[0];   // (2048, 8192)
    const float* blocks = (const float*)d_in[1];   // (8, 256, 256)
    const float* bias   = (const float*)d_in[2];   // (2048,)
    float* out          = (float*)d_out;           // (2048, 8192)

    static int configured = 0;
    if (!configured) {
        cudaFuncSetAttribute(block_linear_fused,
                             cudaFuncAttributeMaxDynamicSharedMemorySize, SMEM_BYTES);
        configured = 1;
    }

    split_A<<<512, 256>>>(blocks);
    dim3 g2(128, 8);   // 128 n-tiles of 64, 8 diagonal blocks
    block_linear_fused<<<g2, 256, SMEM_BYTES>>>(inp, bias, out);
}

// round 15
// speedup vs baseline: 1.0948x; 1.0948x over previous
#include <cuda_runtime.h>
#include <cuda_fp16.h>
#include <cstdint>

// BlockLinear: out = block_diag(blocks) @ inp + bias (fp32 in/out)
//   kA: blocks -> g_Ah fp16  (tiny pre-pass)
//   k2: fused GEMM: CTA = 256m x 128n x 256k, 512 threads,
//       B loaded f32 from inp -> fp16 smem in-register; 3-stage ring, 1 sync/iter.
// Error: A and B each rounded once to fp16 -> global RMS rel err ~2.9e-4 (<1e-3).

typedef unsigned int u32;

__device__ __half g_Ah[8 * 256 * 256];

__device__ __forceinline__ u32 smem_u32(const void* p) {
    u32 a;
    asm("{ .reg .u64 t; cvta.to.shared.u64 t, %1; cvt.u32.u64 %0, t; }" : "=r"(a) : "l"(p));
    return a;
}

// ---------------- kernel A: blocks -> fp16 ----------------
__global__ __launch_bounds__(256)
void split_A(const float* __restrict__ blocks)
{
    const int base = (blockIdx.x * 256 + threadIdx.x) * 4;
    float4 v = *(const float4*)(blocks + base);
    __half2 h01 = __floats2half2_rn(v.x, v.y);
    __half2 h23 = __floats2half2_rn(v.z, v.w);
    uint2 ph;
    ph.x = *reinterpret_cast<u32*>(&h01);
    ph.y = *reinterpret_cast<u32*>(&h23);
    *(uint2*)(g_Ah + base) = ph;
}

// ---------------- fused GEMM ----------------
#define BK 32
#define OFF_A  0            // A tile: 256 rows x 64B = 16 KB
#define OFF_B  16384        // B tile: 32 rows x 256B = 8 KB
#define STAGE_STRIDE 24576
#define NSTAGE 3
#define SMEM_BYTES (NSTAGE * STAGE_STRIDE)   // 72 KB

// A tile: row-major m x k fp16, 64B rows, 4x16B chunks, XOR swizzle (verified)
__device__ __forceinline__ u32 soff(u32 r, u32 k) {
    return r * 64u + ((((k >> 3) ^ ((r >> 1) & 3u))) << 4) + ((k & 7u) << 1);
}
__device__ __forceinline__ u32 schunk(u32 r, u32 c) {
    return r * 64u + ((c ^ ((r >> 1) & 3u)) << 4);
}
// B tile: 32 k-rows x 128 n fp16, 256B rows, 16x16B chunks, chunk ^= (k&7) (verified)
__device__ __forceinline__ u32 bchunk(u32 k, u32 nc) {
    return k * 256u + ((nc ^ (k & 7u)) << 4);
}

__device__ __forceinline__ void ldsm4(u32& r0, u32& r1, u32& r2, u32& r3, u32 addr) {
    asm volatile("ldmatrix.sync.aligned.m8n8.x4.shared.b16 {%0,%1,%2,%3}, [%4];"
                 : "=r"(r0), "=r"(r1), "=r"(r2), "=r"(r3) : "r"(addr));
}
__device__ __forceinline__ void ldsm4t(u32& r0, u32& r1, u32& r2, u32& r3, u32 addr) {
    asm volatile("ldmatrix.sync.aligned.m8n8.x4.trans.shared.b16 {%0,%1,%2,%3}, [%4];"
                 : "=r"(r0), "=r"(r1), "=r"(r2), "=r"(r3) : "r"(addr));
}
__device__ __forceinline__ void mma16816(float* c, const u32* a, u32 b0, u32 b1) {
    asm volatile(
        "mma.sync.aligned.m16n8k16.row.col.f32.f16.f16.f32 "
        "{%0,%1,%2,%3}, {%4,%5,%6,%7}, {%8,%9}, {%0,%1,%2,%3};"
        : "+f"(c[0]), "+f"(c[1]), "+f"(c[2]), "+f"(c[3])
        : "r"(a[0]), "r"(a[1]), "r"(a[2]), "r"(a[3]), "r"(b0), "r"(b1));
}
__device__ __forceinline__ void cp16(u32 dst, const void* src) {
    asm volatile("cp.async.cg.shared.global [%0], [%1], 16;" :: "r"(dst), "l"(src));
}

__global__ __launch_bounds__(512, 1)
void block_linear_fused(const float* __restrict__ inp,
                        const float* __restrict__ bias,
                        float* __restrict__ out)
{
    extern __shared__ char smem[];
    const u32 sb = smem_u32(smem);

    const int tid  = threadIdx.x;
    const int lane = tid & 31;
    const int wid  = tid >> 5;
    const int wm   = wid & 7;        // 8 warp rows x 32
    const int wn   = wid >> 3;       // 2 warp cols x 64

    const int nTile = blockIdx.x;
    const int kblk  = blockIdx.y;
    const int n0    = nTile * 128;

    const __half* Ag = g_Ah + (size_t)kblk * 65536;                 // [256][256] fp16
    const float*  Bg = inp + (size_t)(kblk * 256) * 8192 + n0;      // [256][128] f32 strip
    float*        C  = out + (size_t)(kblk * 256) * 8192 + n0;
    const float*  biasp = bias + kblk * 256;

    // A loader: 512 threads, row = tid>>1 (0..255), chunks (tid&1)*2+{0,1}
    const int alr = tid >> 1;
    const int alc = (tid & 1) * 2;
    // B loader: row k = tid>>4 (0..31), 16B-chunk nc = tid&15, 8 f32 from global
    const int blr = tid >> 4;
    const int bnc = tid & 15;

    float4 bpf0, bpf1;   // B prefetch registers (8 f32)

    float acc[2][8][4];
    #pragma unroll
    for (int i = 0; i < 2; i++)
        #pragma unroll
        for (int j = 0; j < 8; j++)
            #pragma unroll
            for (int q = 0; q < 4; q++) acc[i][j][q] = 0.f;

    auto ldg_B = [&](int c) {
        const float* p = Bg + (size_t)(c * BK + blr) * 8192 + bnc * 8;
        bpf0 = *(const float4*)(p);
        bpf1 = *(const float4*)(p + 4);
    };
    auto sts_B = [&](int c) {
        __half2 h0 = __floats2half2_rn(bpf0.x, bpf0.y);
        __half2 h1 = __floats2half2_rn(bpf0.z, bpf0.w);
        __half2 h2 = __floats2half2_rn(bpf1.x, bpf1.y);
        __half2 h3 = __floats2half2_rn(bpf1.z, bpf1.w);
        uint4 o;
        o.x = *reinterpret_cast<u32*>(&h0);
        o.y = *reinterpret_cast<u32*>(&h1);
        o.z = *reinterpret_cast<u32*>(&h2);
        o.w = *reinterpret_cast<u32*>(&h3);
        *(uint4*)(smem + (c % NSTAGE) * STAGE_STRIDE + OFF_B + bchunk((u32)blr, (u32)bnc)) = o;
    };
    auto cpa_A = [&](int c) {
        const u32 st = sb + (u32)(c % NSTAGE) * STAGE_STRIDE;
        const int k0 = c * BK;
        #pragma unroll
        for (int j = 0; j < 2; ++j) {
            const int ch = alc + j;
            cp16(st + OFF_A + schunk((u32)alr, (u32)ch),
                 Ag + (size_t)alr * 256 + k0 + ch * 8);
        }
    };

    // ---- prologue: B(0) in smem, B(1) in regs, A(0),A(1) committed ----
    ldg_B(0);
    cpa_A(0); asm volatile("cp.async.commit_group;" ::: "memory");
    sts_B(0);
    ldg_B(1);
    cpa_A(1); asm volatile("cp.async.commit_group;" ::: "memory");

    const u32 kl  = (u32)(((lane >> 4) << 3) + (lane & 7));
    const u32 ncl = (u32)((lane >> 3) & 1);

    #pragma unroll 1
    for (int c = 0; c < 8; ++c) {
        asm volatile("cp.async.wait_group 1;" ::: "memory");   // A(c) complete
        __syncthreads();
        // stage c fully written (A via cp.async, B via sts at iter c-1).
        // stage (c+1)%3 last read at iter c-2 -> free for sts_B now.
        // stage (c+2)%3 last read at iter c-1 -> free for cp.async now.

        if (c + 1 < 8) sts_B(c + 1);
        if (c + 2 < 8) {
            ldg_B(c + 2);               // latency covered by compute(c) + compute(c+1)
            cpa_A(c + 2);
        }
        asm volatile("cp.async.commit_group;" ::: "memory");   // empty near tail: ok

        // ---- compute(c) on stage c%3 ----
        const u32 buf = sb + (u32)(c % NSTAGE) * STAGE_STRIDE;
        #pragma unroll
        for (int kk = 0; kk < 2; ++kk) {
            const u32 krow = (u32)(kk * 16);
            const u32 am   = (u32)(wm * 32 + (lane & 15));
            const u32 akr  = krow + (u32)((lane >> 4) << 3);

            u32 aH[2][4], bH[4][4];
            #pragma unroll
            for (int i = 0; i < 2; i++)
                ldsm4(aH[i][0], aH[i][1], aH[i][2], aH[i][3],
                      buf + OFF_A + soff(am + i * 16, akr));
            #pragma unroll
            for (int p = 0; p < 4; p++) {
                const u32 ncb = (u32)(wn * 8 + p * 2) + ncl;
                ldsm4t(bH[p][0], bH[p][1], bH[p][2], bH[p][3],
                       buf + OFF_B + bchunk(krow + kl, ncb));
            }
            #pragma unroll
            for (int i = 0; i < 2; i++)
                #pragma unroll
                for (int p = 0; p < 4; p++) {
                    mma16816(acc[i][2*p],   aH[i], bH[p][0], bH[p][2]);
                    mma16816(acc[i][2*p+1], aH[i], bH[p][1], bH[p][3]);
                }
        }
    }

    // ---- epilogue: bias + store (verified mapping) ----
    #pragma unroll
    for (int i = 0; i < 2; i++) {
        const int r0 = wm * 32 + i * 16 + (lane >> 2);
        const float b0 = biasp[r0];
        const float b1 = biasp[r0 + 8];
        float* p0 = C + (size_t)r0 * 8192;
        float* p1 = C + (size_t)(r0 + 8) * 8192;
        #pragma unroll
        for (int j = 0; j < 8; j++) {
            const int col = wn * 64 + j * 8 + (lane & 3) * 2;
            *(float2*)(p0 + col) = make_float2(acc[i][j][0] + b0, acc[i][j][1] + b0);
            *(float2*)(p1 + col) = make_float2(acc[i][j][2] + b1, acc[i][j][3] + b1);
        }
    }
}

extern "C" void kernel_launch(void* const* d_in, const int* in_sizes, int n_in,
                              void* d_out, int out_size)
{
    const float* inp    = (const float*)d_in[0];   // (2048, 8192)
    const float* blocks = (const float*)d_in[1];   // (8, 256, 256)
    const float* bias   = (const float*)d_in[2];   // (2048,)
    float* out          = (float*)d_out;           // (2048, 8192)

    static int configured = 0;
    if (!configured) {
        cudaFuncSetAttribute(block_linear_fused,
                             cudaFuncAttributeMaxDynamicSharedMemorySize, SMEM_BYTES);
        configured = 1;
    }

    split_A<<<512, 256>>>(blocks);
    dim3 g2(64, 8);   // 64 n-tiles of 128, 8 diagonal blocks
    block_linear_fused<<<g2, 512, SMEM_BYTES>>>(inp, bias, out);
}

// round 17
// speedup vs baseline: 1.1400x; 1.0413x over previous
#include <cuda_runtime.h>
#include <cuda_fp16.h>
#include <cstdint>

// BlockLinear: out = block_diag(blocks) @ inp + bias (fp32 in/out)
//   kA: blocks -> g_Ah fp16  (tiny pre-pass)
//   k2: fused GEMM: CTA = 128m x 128n x 256k, 256 threads, 2 CTAs/SM,
//       B loaded f32 from inp -> fp16 smem in-register; 3-stage ring, 1 sync/iter.
// Error: A and B each rounded once to fp16 -> global RMS rel err ~2.9e-4 (<1e-3).

typedef unsigned int u32;

__device__ __half g_Ah[8 * 256 * 256];

__device__ __forceinline__ u32 smem_u32(const void* p) {
    u32 a;
    asm("{ .reg .u64 t; cvta.to.shared.u64 t, %1; cvt.u32.u64 %0, t; }" : "=r"(a) : "l"(p));
    return a;
}

// ---------------- kernel A: blocks -> fp16 ----------------
__global__ __launch_bounds__(256)
void split_A(const float* __restrict__ blocks)
{
    const int base = (blockIdx.x * 256 + threadIdx.x) * 4;
    float4 v = *(const float4*)(blocks + base);
    __half2 h01 = __floats2half2_rn(v.x, v.y);
    __half2 h23 = __floats2half2_rn(v.z, v.w);
    uint2 ph;
    ph.x = *reinterpret_cast<u32*>(&h01);
    ph.y = *reinterpret_cast<u32*>(&h23);
    *(uint2*)(g_Ah + base) = ph;
}

// ---------------- fused GEMM ----------------
#define BK 32
#define OFF_A  0            // A tile: 128 rows x 64B = 8 KB
#define OFF_B  8192         // B tile: 32 rows x 256B = 8 KB
#define STAGE_STRIDE 16384
#define NSTAGE 3
#define SMEM_BYTES (NSTAGE * STAGE_STRIDE)   // 48 KB -> 2 CTAs/SM

// A tile: row-major m x k fp16, 64B rows, 4x16B chunks, XOR swizzle (verified)
__device__ __forceinline__ u32 soff(u32 r, u32 k) {
    return r * 64u + ((((k >> 3) ^ ((r >> 1) & 3u))) << 4) + ((k & 7u) << 1);
}
__device__ __forceinline__ u32 schunk(u32 r, u32 c) {
    return r * 64u + ((c ^ ((r >> 1) & 3u)) << 4);
}
// B tile: 32 k-rows x 128 n fp16, 256B rows, 16x16B chunks, chunk ^= (k&7) (verified)
__device__ __forceinline__ u32 bchunk(u32 k, u32 nc) {
    return k * 256u + ((nc ^ (k & 7u)) << 4);
}

__device__ __forceinline__ void ldsm4(u32& r0, u32& r1, u32& r2, u32& r3, u32 addr) {
    asm volatile("ldmatrix.sync.aligned.m8n8.x4.shared.b16 {%0,%1,%2,%3}, [%4];"
                 : "=r"(r0), "=r"(r1), "=r"(r2), "=r"(r3) : "r"(addr));
}
__device__ __forceinline__ void ldsm4t(u32& r0, u32& r1, u32& r2, u32& r3, u32 addr) {
    asm volatile("ldmatrix.sync.aligned.m8n8.x4.trans.shared.b16 {%0,%1,%2,%3}, [%4];"
                 : "=r"(r0), "=r"(r1), "=r"(r2), "=r"(r3) : "r"(addr));
}
__device__ __forceinline__ void mma16816(float* c, const u32* a, u32 b0, u32 b1) {
    asm volatile(
        "mma.sync.aligned.m16n8k16.row.col.f32.f16.f16.f32 "
        "{%0,%1,%2,%3}, {%4,%5,%6,%7}, {%8,%9}, {%0,%1,%2,%3};"
        : "+f"(c[0]), "+f"(c[1]), "+f"(c[2]), "+f"(c[3])
        : "r"(a[0]), "r"(a[1]), "r"(a[2]), "r"(a[3]), "r"(b0), "r"(b1));
}
__device__ __forceinline__ void cp16(u32 dst, const void* src) {
    asm volatile("cp.async.cg.shared.global [%0], [%1], 16;" :: "r"(dst), "l"(src));
}

__global__ __launch_bounds__(256, 2)
void block_linear_fused(const float* __restrict__ inp,
                        const float* __restrict__ bias,
                        float* __restrict__ out)
{
    extern __shared__ char smem[];
    const u32 sb = smem_u32(smem);

    const int tid  = threadIdx.x;
    const int lane = tid & 31;
    const int wid  = tid >> 5;
    const int wm   = wid & 3;        // 4 warp rows x 32
    const int wn   = wid >> 2;       // 2 warp cols x 64

    const int nTile = blockIdx.x;
    const int mTile = blockIdx.y;
    const int kblk  = blockIdx.z;
    const int n0    = nTile * 128;

    const __half* Ag = g_Ah + (size_t)kblk * 65536 + (size_t)mTile * 128 * 256;  // [128][256]
    const float*  Bg = inp + (size_t)(kblk * 256) * 8192 + n0;                    // [256][128] f32
    float*        C  = out + (size_t)(kblk * 256 + mTile * 128) * 8192 + n0;
    const float*  biasp = bias + kblk * 256 + mTile * 128;

    // A loader: row = tid>>1 (0..127), chunks (tid&1)*2 + {0,1}
    const int alr = tid >> 1;
    const int alc = (tid & 1) * 2;
    // B loader: row k = tid>>3 (0..31), chunk pair nc0 = (tid&7)*2; 16 f32 source
    const int blr = tid >> 3;
    const int bn0 = (tid & 7) * 16;   // f32 col base

    float4 bpf[4];   // 16 f32 prefetch

    float acc[2][8][4];
    #pragma unroll
    for (int i = 0; i < 2; i++)
        #pragma unroll
        for (int j = 0; j < 8; j++)
            #pragma unroll
            for (int q = 0; q < 4; q++) acc[i][j][q] = 0.f;

    auto ldg_B = [&](int c) {
        const float* p = Bg + (size_t)(c * BK + blr) * 8192 + bn0;
        bpf[0] = *(const float4*)(p);
        bpf[1] = *(const float4*)(p + 4);
        bpf[2] = *(const float4*)(p + 8);
        bpf[3] = *(const float4*)(p + 12);
    };
    auto sts_B = [&](int c) {
        char* base = smem + (c % NSTAGE) * STAGE_STRIDE + OFF_B;
        #pragma unroll
        for (int j = 0; j < 2; ++j) {
            __half2 h0 = __floats2half2_rn(bpf[2*j].x,   bpf[2*j].y);
            __half2 h1 = __floats2half2_rn(bpf[2*j].z,   bpf[2*j].w);
            __half2 h2 = __floats2half2_rn(bpf[2*j+1].x, bpf[2*j+1].y);
            __half2 h3 = __floats2half2_rn(bpf[2*j+1].z, bpf[2*j+1].w);
            uint4 o;
            o.x = *reinterpret_cast<u32*>(&h0);
            o.y = *reinterpret_cast<u32*>(&h1);
            o.z = *reinterpret_cast<u32*>(&h2);
            o.w = *reinterpret_cast<u32*>(&h3);
            *(uint4*)(base + bchunk((u32)blr, (u32)((tid & 7) * 2 + j))) = o;
        }
    };
    auto cpa_A = [&](int c) {
        const u32 st = sb + (u32)(c % NSTAGE) * STAGE_STRIDE;
        const int k0 = c * BK;
        #pragma unroll
        for (int j = 0; j < 2; ++j) {
            const int ch = alc + j;
            cp16(st + OFF_A + schunk((u32)alr, (u32)ch),
                 Ag + (size_t)alr * 256 + k0 + ch * 8);
        }
    };

    // ---- prologue: B(0) in smem, B(1) in regs, A(0),A(1) committed ----
    ldg_B(0);
    cpa_A(0); asm volatile("cp.async.commit_group;" ::: "memory");
    sts_B(0);
    ldg_B(1);
    cpa_A(1); asm volatile("cp.async.commit_group;" ::: "memory");

    const u32 kl  = (u32)(((lane >> 4) << 3) + (lane & 7));
    const u32 ncl = (u32)((lane >> 3) & 1);

    #pragma unroll 1
    for (int c = 0; c < 8; ++c) {
        asm volatile("cp.async.wait_group 1;" ::: "memory");   // A(c) complete
        __syncthreads();
        // stage c ready (A cp.async + B sts at iter c-1).
        // stage (c+1)%3 last read at c-2 -> free; stage (c+2)%3 last read at c-1 -> free.

        if (c + 1 < 8) sts_B(c + 1);
        if (c + 2 < 8) {
            ldg_B(c + 2);
            cpa_A(c + 2);
        }
        asm volatile("cp.async.commit_group;" ::: "memory");

        // ---- compute(c) on stage c%3 ----
        const u32 buf = sb + (u32)(c % NSTAGE) * STAGE_STRIDE;
        #pragma unroll
        for (int kk = 0; kk < 2; ++kk) {
            const u32 krow = (u32)(kk * 16);
            const u32 am   = (u32)(wm * 32 + (lane & 15));
            const u32 akr  = krow + (u32)((lane >> 4) << 3);

            u32 aH[2][4], bH[4][4];
            #pragma unroll
            for (int i = 0; i < 2; i++)
                ldsm4(aH[i][0], aH[i][1], aH[i][2], aH[i][3],
                      buf + OFF_A + soff(am + i * 16, akr));
            #pragma unroll
            for (int p = 0; p < 4; p++) {
                const u32 ncb = (u32)(wn * 8 + p * 2) + ncl;
                ldsm4t(bH[p][0], bH[p][1], bH[p][2], bH[p][3],
                       buf + OFF_B + bchunk(krow + kl, ncb));
            }
            #pragma unroll
            for (int i = 0; i < 2; i++)
                #pragma unroll
                for (int p = 0; p < 4; p++) {
                    mma16816(acc[i][2*p],   aH[i], bH[p][0], bH[p][2]);
                    mma16816(acc[i][2*p+1], aH[i], bH[p][1], bH[p][3]);
                }
        }
    }

    // ---- epilogue: bias + store (verified round-9 mapping) ----
    #pragma unroll
    for (int i = 0; i < 2; i++) {
        const int r0 = wm * 32 + i * 16 + (lane >> 2);
        const float b0 = biasp[r0];
        const float b1 = biasp[r0 + 8];
        float* p0 = C + (size_t)r0 * 8192;
        float* p1 = C + (size_t)(r0 + 8) * 8192;
        #pragma unroll
        for (int j = 0; j < 8; j++) {
            const int col = wn * 64 + j * 8 + (lane & 3) * 2;
            *(float2*)(p0 + col) = make_float2(acc[i][j][0] + b0, acc[i][j][1] + b0);
            *(float2*)(p1 + col) = make_float2(acc[i][j][2] + b1, acc[i][j][3] + b1);
        }
    }
}

extern "C" void kernel_launch(void* const* d_in, const int* in_sizes, int n_in,
                              void* d_out, int out_size)
{
    const float* inp    = (const float*)d_in[0];   // (2048, 8192)
    const float* blocks = (const float*)d_in[1];   // (8, 256, 256)
    const float* bias   = (const float*)d_in[2];   // (2048,)
    float* out          = (float*)d_out;           // (2048, 8192)

    static int configured = 0;
    if (!configured) {
        cudaFuncSetAttribute(block_linear_fused,
                             cudaFuncAttributeMaxDynamicSharedMemorySize, SMEM_BYTES);
        configured = 1;
    }

    split_A<<<512, 256>>>(blocks);
    dim3 g2(64, 2, 8);   // nTile, mTile, kblk
    block_linear_fused<<<g2, 256, SMEM_BYTES>>>(inp, bias, out);
}